// round 15
// baseline (speedup 1.0000x reference)
#include <cuda_runtime.h>
#include <cuda_bf16.h>
#include <cstdint>
#include <math.h>

// ---------------------------------------------------------------------------
// TemporalAttention: B=4, S=2048, D=512, H=8, hd=64, MAX_LAG=10
// R14: attn reverted to QBLK=16 (R12-measured best); merged convert kept;
// GEMM B-fragments register-pipelined (prefetch ni+1 while issuing ni's MMAs)
// -- per-acc contribution order unchanged => bitwise-identical results.
// ---------------------------------------------------------------------------

#define BATCH   4
#define SEQ     2048
#define DMODEL  512
#define NHEADS  8
#define HDIM    64
#define MAXLAG  10
#define MTOT    (BATCH * SEQ)        // 8192
#define QBLK    16                   // queries per attention block
#define WIN     (QBLK + MAXLAG)      // 26
#define ASMEM   (2 * WIN * DMODEL * 4)   // 106496 B dynamic smem

// ---------------- scratch ----------------------------------------------------
__device__ __nv_bfloat16 g_Xhi[MTOT * DMODEL];
__device__ __nv_bfloat16 g_Xlo[MTOT * DMODEL];
__device__ __nv_bfloat16 g_Chi[MTOT * DMODEL];
__device__ __nv_bfloat16 g_Clo[MTOT * DMODEL];
__device__ __nv_bfloat16 g_WT [4 * 2 * DMODEL * DMODEL]; // [w][hi/lo][n*K+k]
__device__ float g_Q[MTOT * DMODEL];
__device__ float g_K[MTOT * DMODEL];
__device__ float g_V[MTOT * DMODEL];

// ---------------- helpers ----------------------------------------------------
__device__ __forceinline__ uint32_t smem_u32(const void* p) {
    uint32_t a;
    asm("{ .reg .u64 t; cvta.to.shared.u64 t, %1; cvt.u32.u64 %0, t; }"
        : "=r"(a) : "l"(p));
    return a;
}
__device__ __forceinline__ void cpasync16(uint32_t sdst, const void* gsrc) {
    asm volatile("cp.async.cg.shared.global [%0], [%1], 16;"
                 :: "r"(sdst), "l"(gsrc));
}
__device__ __forceinline__ void ldsm_x4(uint32_t* r, uint32_t addr) {
    asm volatile("ldmatrix.sync.aligned.m8n8.x4.shared.b16 {%0,%1,%2,%3}, [%4];"
                 : "=r"(r[0]), "=r"(r[1]), "=r"(r[2]), "=r"(r[3]) : "r"(addr));
}
__device__ __forceinline__ void ldsm_x2(uint32_t* r, uint32_t addr) {
    asm volatile("ldmatrix.sync.aligned.m8n8.x2.shared.b16 {%0,%1}, [%2];"
                 : "=r"(r[0]), "=r"(r[1]) : "r"(addr));
}
__device__ __forceinline__ void mma_bf16(float* d, const uint32_t* a,
                                         const uint32_t* b) {
    asm volatile(
        "mma.sync.aligned.m16n8k16.row.col.f32.bf16.bf16.f32 "
        "{%0,%1,%2,%3}, {%4,%5,%6,%7}, {%8,%9}, {%0,%1,%2,%3};"
        : "+f"(d[0]), "+f"(d[1]), "+f"(d[2]), "+f"(d[3])
        : "r"(a[0]), "r"(a[1]), "r"(a[2]), "r"(a[3]), "r"(b[0]), "r"(b[1]));
}
__device__ __forceinline__ void split2(float a, float b, __nv_bfloat162& hi,
                                       __nv_bfloat162& lo) {
    __nv_bfloat16 ha = __float2bfloat16_rn(a);
    __nv_bfloat16 hb = __float2bfloat16_rn(b);
    __nv_bfloat16 la = __float2bfloat16_rn(a - __bfloat162float(ha));
    __nv_bfloat16 lb = __float2bfloat16_rn(b - __bfloat162float(hb));
    hi = __nv_bfloat162(ha, hb);
    lo = __nv_bfloat162(la, lb);
}

// ---------------------------------------------------------------------------
// merged conversion kernel (R13-measured, kept): blocks [0,4096) split X;
// blocks [4096,5120) transpose+split one 32x32 tile of one of the 4 weights.
// ---------------------------------------------------------------------------
#define XBLOCKS (MTOT * DMODEL / 4 / 256)    // 4096

__global__ __launch_bounds__(256) void convert_all(
    const float* __restrict__ X,
    const float* __restrict__ W0, const float* __restrict__ W1,
    const float* __restrict__ W2, const float* __restrict__ W3,
    __nv_bfloat16* __restrict__ Xhi, __nv_bfloat16* __restrict__ Xlo,
    __nv_bfloat16* __restrict__ WT)
{
    const int bx = blockIdx.x;
    const int tid = threadIdx.x;

    if (bx < XBLOCKS) {
        int i = bx * 256 + tid;
        float4 v = reinterpret_cast<const float4*>(X)[i];
        __nv_bfloat162 h0, l0, h1, l1;
        split2(v.x, v.y, h0, l0);
        split2(v.z, v.w, h1, l1);
        reinterpret_cast<__nv_bfloat162*>(Xhi)[2 * i]     = h0;
        reinterpret_cast<__nv_bfloat162*>(Xhi)[2 * i + 1] = h1;
        reinterpret_cast<__nv_bfloat162*>(Xlo)[2 * i]     = l0;
        reinterpret_cast<__nv_bfloat162*>(Xlo)[2 * i + 1] = l1;
        return;
    }

    const int wb = bx - XBLOCKS;                 // 0..1023
    const int w  = wb >> 8;                      // 0..3
    const int t  = wb & 255;
    const int n0 = (t & 15) * 32, k0 = (t >> 4) * 32;
    const float* W = (w == 0) ? W0 : (w == 1) ? W1 : (w == 2) ? W2 : W3;
    const size_t WSZ = (size_t)DMODEL * DMODEL;
    __nv_bfloat16* hiT = WT + (size_t)(2 * w) * WSZ;
    __nv_bfloat16* loT = hiT + WSZ;

    __shared__ float tile[32][33];
    const int tx = tid & 31, ty = tid >> 5;      // (32, 8)
#pragma unroll
    for (int r = 0; r < 32; r += 8)
        tile[ty + r][tx] = W[(size_t)(k0 + ty + r) * DMODEL + n0 + tx];
    __syncthreads();
#pragma unroll
    for (int r = 0; r < 32; r += 8) {
        float v = tile[tx][ty + r];
        __nv_bfloat16 h = __float2bfloat16_rn(v);
        __nv_bfloat16 l = __float2bfloat16_rn(v - __bfloat162float(h));
        size_t idx = (size_t)(n0 + ty + r) * DMODEL + k0 + tx;
        hiT[idx] = h;
        loT[idx] = l;
    }
}

// ---------------------------------------------------------------------------
// bf16 3-term-split GEMM core: 2-stage cp.async, 2 CTAs/SM, B-fragment
// register pipeline (prefetch ni+1's B while issuing ni's 12 MMAs).
// ---------------------------------------------------------------------------
#define BK        32
#define ROWB      80
#define TILEB     (128 * ROWB)          // 10240
#define STAGEB    (4 * TILEB)           // 40960
#define GSMEM_DYN (2 * STAGEB)          // 81920 -> 2 CTAs/SM
#define NKT       (DMODEL / BK)         // 16

__device__ __forceinline__ void issue_stage(
    uint32_t sbase, const char* pA_hi, const char* pA_lo,
    const char* pB_hi, const char* pB_lo, int kt, int tid)
{
    const size_t koff = (size_t)kt * 64;
    const char* gsrc[4] = { pA_hi, pA_lo, pB_hi, pB_lo };
#pragma unroll
    for (int t = 0; t < 4; t++) {
        uint32_t sdst = sbase + t * TILEB;
#pragma unroll
        for (int q = 0; q < 2; q++) {
            int chunk = tid + q * 256;
            int row = chunk >> 2, c = chunk & 3;
            cpasync16(sdst + row * ROWB + c * 16,
                      gsrc[t] + (size_t)row * 1024 + koff + c * 16);
        }
    }
}

__device__ __forceinline__ void gemm_core(
    const __nv_bfloat16* __restrict__ Ahi, const __nv_bfloat16* __restrict__ Alo,
    const __nv_bfloat16* __restrict__ BhiT, const __nv_bfloat16* __restrict__ BloT,
    const float* __restrict__ bias,
    float* __restrict__ C, int cRow, char* dsm)
{
    const int tid = threadIdx.x;
    const int wid = tid >> 5;
    const int l   = tid & 31;
    const int wm  = wid >> 2;
    const int wn  = wid & 3;

    const uint32_t sbase = smem_u32(dsm);

    const char* pAhi = reinterpret_cast<const char*>(Ahi + (size_t)cRow * DMODEL);
    const char* pAlo = reinterpret_cast<const char*>(Alo + (size_t)cRow * DMODEL);
    const char* pBhi = reinterpret_cast<const char*>(BhiT);
    const char* pBlo = reinterpret_cast<const char*>(BloT);

    float acc[4][4][4] = {};

    issue_stage(sbase, pAhi, pAlo, pBhi, pBlo, 0, tid);
    asm volatile("cp.async.commit_group;" ::: "memory");

    const int aRow = wm * 64 + (l & 15);
    const int aChk = (l >> 4);
    const int bRow = wn * 32 + (l & 7);
    const int bChk = ((l >> 3) & 1);

    for (int kt = 0; kt < NKT; kt++) {
        if (kt + 1 < NKT)
            issue_stage(sbase + ((kt + 1) & 1) * STAGEB,
                        pAhi, pAlo, pBhi, pBlo, kt + 1, tid);
        asm volatile("cp.async.commit_group;" ::: "memory");
        asm volatile("cp.async.wait_group 1;" ::: "memory");
        __syncthreads();

        const uint32_t st = sbase + (kt & 1) * STAGEB;
        const uint32_t sAhi = st,             sAlo = st + TILEB;
        const uint32_t sBhi = st + 2 * TILEB, sBlo = st + 3 * TILEB;

#pragma unroll
        for (int ks = 0; ks < 2; ks++) {
            uint32_t ah[4][4], al[4][4];
#pragma unroll
            for (int mi = 0; mi < 4; mi++) {
                uint32_t off = (aRow + mi * 16) * ROWB + (aChk + 2 * ks) * 16;
                ldsm_x4(ah[mi], sAhi + off);
                ldsm_x4(al[mi], sAlo + off);
            }

            // B register pipeline: 2 live (hi,lo) pairs; prefetch ni+1 while
            // issuing ni's 12 MMAs. Per-acc contribution order is unchanged
            // (ah*bh, al*bh, ah*bl) -> bitwise-identical results.
            uint32_t bhP[2][2], blP[2][2];
            {
                uint32_t off0 = (bRow + 0 * 8) * ROWB + (bChk + 2 * ks) * 16;
                ldsm_x2(bhP[0], sBhi + off0);
                ldsm_x2(blP[0], sBlo + off0);
            }
#pragma unroll
            for (int ni = 0; ni < 4; ni++) {
                const int cur = ni & 1, nxt = cur ^ 1;
                if (ni < 3) {
                    uint32_t off = (bRow + (ni + 1) * 8) * ROWB + (bChk + 2 * ks) * 16;
                    ldsm_x2(bhP[nxt], sBhi + off);
                    ldsm_x2(blP[nxt], sBlo + off);
                }
#pragma unroll
                for (int mi = 0; mi < 4; mi++)
                    mma_bf16(acc[mi][ni], ah[mi], bhP[cur]);
#pragma unroll
                for (int mi = 0; mi < 4; mi++)
                    mma_bf16(acc[mi][ni], al[mi], bhP[cur]);
#pragma unroll
                for (int mi = 0; mi < 4; mi++)
                    mma_bf16(acc[mi][ni], ah[mi], blP[cur]);
            }
        }
        __syncthreads();
    }

#pragma unroll
    for (int mi = 0; mi < 4; mi++) {
        const int r0 = cRow + wm * 64 + mi * 16 + (l >> 2);
#pragma unroll
        for (int ni = 0; ni < 4; ni++) {
            const int cc = wn * 32 + ni * 8 + 2 * (l & 3);
            const float b0 = bias[cc], b1 = bias[cc + 1];
            float2 v0 = { acc[mi][ni][0] + b0, acc[mi][ni][1] + b1 };
            float2 v1 = { acc[mi][ni][2] + b0, acc[mi][ni][3] + b1 };
            *reinterpret_cast<float2*>(C + (size_t)r0 * DMODEL + cc) = v0;
            *reinterpret_cast<float2*>(C + (size_t)(r0 + 8) * DMODEL + cc) = v1;
        }
    }
}

__global__ __launch_bounds__(256) void gemm_qkv(
    const __nv_bfloat16* __restrict__ Ahi, const __nv_bfloat16* __restrict__ Alo,
    const __nv_bfloat16* __restrict__ WT,
    const float* __restrict__ bq, const float* __restrict__ bk,
    const float* __restrict__ bv,
    float* __restrict__ Q, float* __restrict__ K, float* __restrict__ V)
{
    extern __shared__ char dsm[];
    const int w    = blockIdx.x >> 2;            // 0..2
    const int ncol = (blockIdx.x & 3) * 128;
    const int cRow = blockIdx.y * 128;
    const size_t WSZ = (size_t)DMODEL * DMODEL;
    const __nv_bfloat16* Bhi = WT + (size_t)(2 * w) * WSZ + (size_t)ncol * DMODEL;
    const __nv_bfloat16* Blo = Bhi + WSZ;
    const float* bias = ((w == 0) ? bq : (w == 1) ? bk : bv) + ncol;
    float* C = ((w == 0) ? Q : (w == 1) ? K : V) + ncol;
    gemm_core(Ahi, Alo, Bhi, Blo, bias, C, cRow, dsm);
}

__global__ __launch_bounds__(256) void gemm_o(
    const __nv_bfloat16* __restrict__ Ahi, const __nv_bfloat16* __restrict__ Alo,
    const __nv_bfloat16* __restrict__ WT, const float* __restrict__ bo,
    float* __restrict__ C)
{
    extern __shared__ char dsm[];
    const int ncol = blockIdx.x * 128;
    const int cRow = blockIdx.y * 128;
    const size_t WSZ = (size_t)DMODEL * DMODEL;
    const __nv_bfloat16* Bhi = WT + (size_t)6 * WSZ + (size_t)ncol * DMODEL;
    const __nv_bfloat16* Blo = Bhi + WSZ;
    gemm_core(Ahi, Alo, Bhi, Blo, bo + ncol, C + ncol, cRow, dsm);
}

// ---------------------------------------------------------------------------
// Banded causal attention (R12-measured config): 16 queries/block, 512 thr,
// 26-row smem window (swizzle sigma(c)=c^((c>>3)&3)), cp.async staging with
// Q-load + attn_mean zero-fill overlap.
// ---------------------------------------------------------------------------
__global__ __launch_bounds__(512, 2) void attn_banded(
    const float* __restrict__ Q, const float* __restrict__ K,
    const float* __restrict__ V, const float* __restrict__ td,
    __nv_bfloat16* __restrict__ chi, __nv_bfloat16* __restrict__ clo,
    float* __restrict__ attn_mean)
{
    extern __shared__ float s_kv[];              // [2][WIN][512]
    __shared__ float s_d[MAXLAG + 1];

    const int tid = threadIdx.x;
    const int w = tid >> 5;
    const int l = tid & 31;
    const int blk = blockIdx.x;
    const int b  = blk >> 7;                     // 128 blocks per batch
    const int i0 = (blk & 127) * QBLK;
    const int i  = i0 + w;
    const int bi = blk * QBLK + w;               // global row

    if (tid <= MAXLAG) {
        float x = td[tid];
        float sp = (x > 20.f) ? x : log1pf(expf(x));
        s_d[tid] = -logf(sp + 1e-8f);
    }

    // ---- stage the K/V window via cp.async
    const uint32_t skv = smem_u32(s_kv);
    const uint32_t svoff = WIN * DMODEL * 4;
    const int row0 = i0 - MAXLAG;
    const float* Kb = K + (size_t)b * SEQ * DMODEL;
    const float* Vb = V + (size_t)b * SEQ * DMODEL;
#pragma unroll
    for (int q = 0; q < (WIN * 128 + 511) / 512; q++) {
        int g = tid + q * 512;
        if (g < WIN * 128) {
            int widx = g >> 7, c = g & 127;
            int rg = row0 + widx;
            if (rg >= 0) {
                int slot = c ^ ((c >> 3) & 3);
                uint32_t soff = (uint32_t)(widx * DMODEL + slot * 4) * 4;
                cpasync16(skv + soff,         Kb + (size_t)rg * DMODEL + c * 4);
                cpasync16(skv + svoff + soff, Vb + (size_t)rg * DMODEL + c * 4);
            }
        }
    }
    asm volatile("cp.async.commit_group;" ::: "memory");

    // ---- overlap: zero-fill this block's 16 attn_mean rows
    float* ablk = attn_mean + (size_t)b * SEQ * SEQ + (size_t)i0 * SEQ;
    {
        float4 z = {0.f, 0.f, 0.f, 0.f};
#pragma unroll
        for (int r = 0; r < QBLK; r++)
            reinterpret_cast<float4*>(ablk + (size_t)r * SEQ)[tid] = z;
    }

    // ---- overlap: load q while the cp.asyncs fly
    const float4* qp = reinterpret_cast<const float4*>(Q + (size_t)bi * DMODEL + 16 * l);
    float4 q0 = qp[0], q1 = qp[1], q2 = qp[2], q3 = qp[3];

    asm volatile("cp.async.wait_group 0;" ::: "memory");
    __syncthreads();

    const float* sK = s_kv;
    const float* sV = s_kv + WIN * DMODEL;

    int sl[4];
#pragma unroll
    for (int t = 0; t < 4; t++) {
        int c = 4 * l + t;
        sl[t] = (c ^ ((c >> 3) & 3)) * 4;
    }

    const int jstart = (i > MAXLAG) ? (i - MAXLAG) : 0;
    const int nj = i - jstart + 1;

    float sc[MAXLAG + 1];
#pragma unroll
    for (int jj = 0; jj <= MAXLAG; jj++) {
        if (jj < nj) {
            const float* kr = sK + (size_t)(jstart + jj - row0) * DMODEL;
            float4 k0 = *reinterpret_cast<const float4*>(kr + sl[0]);
            float4 k1 = *reinterpret_cast<const float4*>(kr + sl[1]);
            float4 k2 = *reinterpret_cast<const float4*>(kr + sl[2]);
            float4 k3 = *reinterpret_cast<const float4*>(kr + sl[3]);
            float d = q0.x * k0.x + q0.y * k0.y + q0.z * k0.z + q0.w * k0.w
                    + q1.x * k1.x + q1.y * k1.y + q1.z * k1.z + q1.w * k1.w
                    + q2.x * k2.x + q2.y * k2.y + q2.z * k2.z + q2.w * k2.w
                    + q3.x * k3.x + q3.y * k3.y + q3.z * k3.z + q3.w * k3.w;
            d += __shfl_xor_sync(0xffffffffu, d, 1);
            d += __shfl_xor_sync(0xffffffffu, d, 2);
            sc[jj] = d * 0.125f + s_d[i - (jstart + jj)];
        } else {
            sc[jj] = -1e30f;
        }
    }

    float mx = sc[0];
#pragma unroll
    for (int jj = 1; jj <= MAXLAG; jj++) mx = fmaxf(mx, sc[jj]);
    float sum = 0.f;
#pragma unroll
    for (int jj = 0; jj <= MAXLAG; jj++) {
        sc[jj] = expf(sc[jj] - mx);
        sum += sc[jj];
    }
    const float inv = 1.f / sum;

    float4 c0 = {0,0,0,0}, c1 = {0,0,0,0}, c2 = {0,0,0,0}, c3 = {0,0,0,0};
#pragma unroll
    for (int jj = 0; jj <= MAXLAG; jj++) {
        if (jj < nj) {
            const float p = sc[jj] * inv;
            sc[jj] = p;
            const float* vr = sV + (size_t)(jstart + jj - row0) * DMODEL;
            float4 v0 = *reinterpret_cast<const float4*>(vr + sl[0]);
            float4 v1 = *reinterpret_cast<const float4*>(vr + sl[1]);
            float4 v2 = *reinterpret_cast<const float4*>(vr + sl[2]);
            float4 v3 = *reinterpret_cast<const float4*>(vr + sl[3]);
            c0.x = fmaf(p, v0.x, c0.x); c0.y = fmaf(p, v0.y, c0.y);
            c0.z = fmaf(p, v0.z, c0.z); c0.w = fmaf(p, v0.w, c0.w);
            c1.x = fmaf(p, v1.x, c1.x); c1.y = fmaf(p, v1.y, c1.y);
            c1.z = fmaf(p, v1.z, c1.z); c1.w = fmaf(p, v1.w, c1.w);
            c2.x = fmaf(p, v2.x, c2.x); c2.y = fmaf(p, v2.y, c2.y);
            c2.z = fmaf(p, v2.z, c2.z); c2.w = fmaf(p, v2.w, c2.w);
            c3.x = fmaf(p, v3.x, c3.x); c3.y = fmaf(p, v3.y, c3.y);
            c3.z = fmaf(p, v3.z, c3.z); c3.w = fmaf(p, v3.w, c3.w);
        } else {
            sc[jj] = 0.f;
        }
    }

    // ctx as bf16 hi/lo
    {
        __nv_bfloat162* hp = reinterpret_cast<__nv_bfloat162*>(chi) + (size_t)bi * 256 + 8 * l;
        __nv_bfloat162* lp = reinterpret_cast<__nv_bfloat162*>(clo) + (size_t)bi * 256 + 8 * l;
        __nv_bfloat162 h, lo2;
        split2(c0.x, c0.y, h, lo2); hp[0] = h; lp[0] = lo2;
        split2(c0.z, c0.w, h, lo2); hp[1] = h; lp[1] = lo2;
        split2(c1.x, c1.y, h, lo2); hp[2] = h; lp[2] = lo2;
        split2(c1.z, c1.w, h, lo2); hp[3] = h; lp[3] = lo2;
        split2(c2.x, c2.y, h, lo2); hp[4] = h; lp[4] = lo2;
        split2(c2.z, c2.w, h, lo2); hp[5] = h; lp[5] = lo2;
        split2(c3.x, c3.y, h, lo2); hp[6] = h; lp[6] = lo2;
        split2(c3.z, c3.w, h, lo2); hp[7] = h; lp[7] = lo2;
    }

    // attn_mean: butterfly xor 4/8/16 sums each head exactly once
    float* arow = attn_mean + (size_t)b * SEQ * SEQ + (size_t)i * SEQ;
#pragma unroll
    for (int jj = 0; jj <= MAXLAG; jj++) {
        float P = sc[jj];
        P += __shfl_xor_sync(0xffffffffu, P, 4);
        P += __shfl_xor_sync(0xffffffffu, P, 8);
        P += __shfl_xor_sync(0xffffffffu, P, 16);
        if (l == jj && jj < nj)
            arow[jstart + jj] = P * (1.f / NHEADS);
    }
}

// ---------------------------------------------------------------------------
extern "C" void kernel_launch(void* const* d_in, const int* in_sizes, int n_in,
                              void* d_out, int out_size)
{
    const float* x  = (const float*)d_in[0];
    const float* Wq = (const float*)d_in[1];
    const float* bq = (const float*)d_in[2];
    const float* Wk = (const float*)d_in[3];
    const float* bk = (const float*)d_in[4];
    const float* Wv = (const float*)d_in[5];
    const float* bv = (const float*)d_in[6];
    const float* Wo = (const float*)d_in[7];
    const float* bo = (const float*)d_in[8];
    const float* td = (const float*)d_in[9];

    float* out_ptr  = (float*)d_out;
    float* attn_ptr = out_ptr + (size_t)BATCH * SEQ * DMODEL;

    __nv_bfloat16 *Xhi, *Xlo, *Chi, *Clo, *WT;
    float *Qs, *Ks, *Vs;
    cudaGetSymbolAddress((void**)&Xhi, g_Xhi);
    cudaGetSymbolAddress((void**)&Xlo, g_Xlo);
    cudaGetSymbolAddress((void**)&Chi, g_Chi);
    cudaGetSymbolAddress((void**)&Clo, g_Clo);
    cudaGetSymbolAddress((void**)&WT,  g_WT);
    cudaGetSymbolAddress((void**)&Qs,  g_Q);
    cudaGetSymbolAddress((void**)&Ks,  g_K);
    cudaGetSymbolAddress((void**)&Vs,  g_V);

    cudaFuncSetAttribute(gemm_qkv,
                         cudaFuncAttributeMaxDynamicSharedMemorySize, GSMEM_DYN);
    cudaFuncSetAttribute(gemm_o,
                         cudaFuncAttributeMaxDynamicSharedMemorySize, GSMEM_DYN);
    cudaFuncSetAttribute(attn_banded,
                         cudaFuncAttributeMaxDynamicSharedMemorySize, ASMEM);

    // 1) merged conversions (X split + 4 weight transpose/splits, one launch)
    convert_all<<<XBLOCKS + 1024, 256>>>(x, Wq, Wk, Wv, Wo, Xhi, Xlo, WT);

    // 2) fused QKV projection -> separate Q/K/V buffers
    dim3 gq(12, MTOT / 128);
    gemm_qkv<<<gq, 256, GSMEM_DYN>>>(Xhi, Xlo, WT, bq, bk, bv, Qs, Ks, Vs);

    // 3) banded attention (16 queries/block; zero-fills its attn_mean rows)
    attn_banded<<<MTOT / QBLK, 512, ASMEM>>>(Qs, Ks, Vs, td, Chi, Clo, attn_ptr);

    // 4) O projection straight into d_out
    dim3 go(DMODEL / 128, MTOT / 128);
    gemm_o<<<go, 256, GSMEM_DYN>>>(Chi, Clo, WT, bo, out_ptr);
}

// round 16
// speedup vs baseline: 1.0424x; 1.0424x over previous
#include <cuda_runtime.h>
#include <cuda_bf16.h>
#include <cstdint>
#include <math.h>

// ---------------------------------------------------------------------------
// TemporalAttention: B=4, S=2048, D=512, H=8, hd=64, MAX_LAG=10
// R15: exact R12 GEMM + attn kernels (measured best, 239.6us); single delta =
// merged conversion launch (convert_all). GEMM sits on the 128-reg/2-CTA RF
// cliff -- do not add live registers (R14 lesson: 130 regs -> 1 CTA/SM).
// ---------------------------------------------------------------------------

#define BATCH   4
#define SEQ     2048
#define DMODEL  512
#define NHEADS  8
#define HDIM    64
#define MAXLAG  10
#define MTOT    (BATCH * SEQ)        // 8192
#define QBLK    16                   // queries per attention block
#define WIN     (QBLK + MAXLAG)      // 26
#define ASMEM   (2 * WIN * DMODEL * 4)   // 106496 B dynamic smem

// ---------------- scratch ----------------------------------------------------
__device__ __nv_bfloat16 g_Xhi[MTOT * DMODEL];
__device__ __nv_bfloat16 g_Xlo[MTOT * DMODEL];
__device__ __nv_bfloat16 g_Chi[MTOT * DMODEL];
__device__ __nv_bfloat16 g_Clo[MTOT * DMODEL];
__device__ __nv_bfloat16 g_WT [4 * 2 * DMODEL * DMODEL]; // [w][hi/lo][n*K+k]
__device__ float g_Q[MTOT * DMODEL];
__device__ float g_K[MTOT * DMODEL];
__device__ float g_V[MTOT * DMODEL];

// ---------------- helpers ----------------------------------------------------
__device__ __forceinline__ uint32_t smem_u32(const void* p) {
    uint32_t a;
    asm("{ .reg .u64 t; cvta.to.shared.u64 t, %1; cvt.u32.u64 %0, t; }"
        : "=r"(a) : "l"(p));
    return a;
}
__device__ __forceinline__ void cpasync16(uint32_t sdst, const void* gsrc) {
    asm volatile("cp.async.cg.shared.global [%0], [%1], 16;"
                 :: "r"(sdst), "l"(gsrc));
}
__device__ __forceinline__ void ldsm_x4(uint32_t* r, uint32_t addr) {
    asm volatile("ldmatrix.sync.aligned.m8n8.x4.shared.b16 {%0,%1,%2,%3}, [%4];"
                 : "=r"(r[0]), "=r"(r[1]), "=r"(r[2]), "=r"(r[3]) : "r"(addr));
}
__device__ __forceinline__ void ldsm_x2(uint32_t* r, uint32_t addr) {
    asm volatile("ldmatrix.sync.aligned.m8n8.x2.shared.b16 {%0,%1}, [%2];"
                 : "=r"(r[0]), "=r"(r[1]) : "r"(addr));
}
__device__ __forceinline__ void mma_bf16(float* d, const uint32_t* a,
                                         const uint32_t* b) {
    asm volatile(
        "mma.sync.aligned.m16n8k16.row.col.f32.bf16.bf16.f32 "
        "{%0,%1,%2,%3}, {%4,%5,%6,%7}, {%8,%9}, {%0,%1,%2,%3};"
        : "+f"(d[0]), "+f"(d[1]), "+f"(d[2]), "+f"(d[3])
        : "r"(a[0]), "r"(a[1]), "r"(a[2]), "r"(a[3]), "r"(b[0]), "r"(b[1]));
}
__device__ __forceinline__ void split2(float a, float b, __nv_bfloat162& hi,
                                       __nv_bfloat162& lo) {
    __nv_bfloat16 ha = __float2bfloat16_rn(a);
    __nv_bfloat16 hb = __float2bfloat16_rn(b);
    __nv_bfloat16 la = __float2bfloat16_rn(a - __bfloat162float(ha));
    __nv_bfloat16 lb = __float2bfloat16_rn(b - __bfloat162float(hb));
    hi = __nv_bfloat162(ha, hb);
    lo = __nv_bfloat162(la, lb);
}

// ---------------------------------------------------------------------------
// merged conversion: blocks [0,4096) split X; blocks [4096,5120) transpose+
// split one 32x32 tile of one of the 4 weights.
// ---------------------------------------------------------------------------
#define XBLOCKS (MTOT * DMODEL / 4 / 256)    // 4096

__global__ __launch_bounds__(256) void convert_all(
    const float* __restrict__ X,
    const float* __restrict__ W0, const float* __restrict__ W1,
    const float* __restrict__ W2, const float* __restrict__ W3,
    __nv_bfloat16* __restrict__ Xhi, __nv_bfloat16* __restrict__ Xlo,
    __nv_bfloat16* __restrict__ WT)
{
    const int bx = blockIdx.x;
    const int tid = threadIdx.x;

    if (bx < XBLOCKS) {
        int i = bx * 256 + tid;
        float4 v = reinterpret_cast<const float4*>(X)[i];
        __nv_bfloat162 h0, l0, h1, l1;
        split2(v.x, v.y, h0, l0);
        split2(v.z, v.w, h1, l1);
        reinterpret_cast<__nv_bfloat162*>(Xhi)[2 * i]     = h0;
        reinterpret_cast<__nv_bfloat162*>(Xhi)[2 * i + 1] = h1;
        reinterpret_cast<__nv_bfloat162*>(Xlo)[2 * i]     = l0;
        reinterpret_cast<__nv_bfloat162*>(Xlo)[2 * i + 1] = l1;
        return;
    }

    const int wb = bx - XBLOCKS;                 // 0..1023
    const int w  = wb >> 8;                      // 0..3
    const int t  = wb & 255;
    const int n0 = (t & 15) * 32, k0 = (t >> 4) * 32;
    const float* W = (w == 0) ? W0 : (w == 1) ? W1 : (w == 2) ? W2 : W3;
    const size_t WSZ = (size_t)DMODEL * DMODEL;
    __nv_bfloat16* hiT = WT + (size_t)(2 * w) * WSZ;
    __nv_bfloat16* loT = hiT + WSZ;

    __shared__ float tile[32][33];
    const int tx = tid & 31, ty = tid >> 5;      // (32, 8)
#pragma unroll
    for (int r = 0; r < 32; r += 8)
        tile[ty + r][tx] = W[(size_t)(k0 + ty + r) * DMODEL + n0 + tx];
    __syncthreads();
#pragma unroll
    for (int r = 0; r < 32; r += 8) {
        float v = tile[tx][ty + r];
        __nv_bfloat16 h = __float2bfloat16_rn(v);
        __nv_bfloat16 l = __float2bfloat16_rn(v - __bfloat162float(h));
        size_t idx = (size_t)(n0 + ty + r) * DMODEL + k0 + tx;
        hiT[idx] = h;
        loT[idx] = l;
    }
}

// ---------------------------------------------------------------------------
// bf16 3-term-split GEMM core (R12 exact: 2-stage cp.async, 2 CTAs/SM,
// term-major MMAs, ldsm_x2 B-loads; regs = 128 -- DO NOT add live registers)
// ---------------------------------------------------------------------------
#define BK        32
#define ROWB      80
#define TILEB     (128 * ROWB)          // 10240
#define STAGEB    (4 * TILEB)           // 40960
#define GSMEM_DYN (2 * STAGEB)          // 81920 -> 2 CTAs/SM
#define NKT       (DMODEL / BK)         // 16

__device__ __forceinline__ void issue_stage(
    uint32_t sbase, const char* pA_hi, const char* pA_lo,
    const char* pB_hi, const char* pB_lo, int kt, int tid)
{
    const size_t koff = (size_t)kt * 64;
    const char* gsrc[4] = { pA_hi, pA_lo, pB_hi, pB_lo };
#pragma unroll
    for (int t = 0; t < 4; t++) {
        uint32_t sdst = sbase + t * TILEB;
#pragma unroll
        for (int q = 0; q < 2; q++) {
            int chunk = tid + q * 256;
            int row = chunk >> 2, c = chunk & 3;
            cpasync16(sdst + row * ROWB + c * 16,
                      gsrc[t] + (size_t)row * 1024 + koff + c * 16);
        }
    }
}

__device__ __forceinline__ void gemm_core(
    const __nv_bfloat16* __restrict__ Ahi, const __nv_bfloat16* __restrict__ Alo,
    const __nv_bfloat16* __restrict__ BhiT, const __nv_bfloat16* __restrict__ BloT,
    const float* __restrict__ bias,
    float* __restrict__ C, int cRow, char* dsm)
{
    const int tid = threadIdx.x;
    const int wid = tid >> 5;
    const int l   = tid & 31;
    const int wm  = wid >> 2;
    const int wn  = wid & 3;

    const uint32_t sbase = smem_u32(dsm);

    const char* pAhi = reinterpret_cast<const char*>(Ahi + (size_t)cRow * DMODEL);
    const char* pAlo = reinterpret_cast<const char*>(Alo + (size_t)cRow * DMODEL);
    const char* pBhi = reinterpret_cast<const char*>(BhiT);
    const char* pBlo = reinterpret_cast<const char*>(BloT);

    float acc[4][4][4] = {};

    issue_stage(sbase, pAhi, pAlo, pBhi, pBlo, 0, tid);
    asm volatile("cp.async.commit_group;" ::: "memory");

    const int aRow = wm * 64 + (l & 15);
    const int aChk = (l >> 4);
    const int bRow = wn * 32 + (l & 7);
    const int bChk = ((l >> 3) & 1);

    for (int kt = 0; kt < NKT; kt++) {
        if (kt + 1 < NKT)
            issue_stage(sbase + ((kt + 1) & 1) * STAGEB,
                        pAhi, pAlo, pBhi, pBlo, kt + 1, tid);
        asm volatile("cp.async.commit_group;" ::: "memory");
        asm volatile("cp.async.wait_group 1;" ::: "memory");
        __syncthreads();

        const uint32_t st = sbase + (kt & 1) * STAGEB;
        const uint32_t sAhi = st,             sAlo = st + TILEB;
        const uint32_t sBhi = st + 2 * TILEB, sBlo = st + 3 * TILEB;

#pragma unroll
        for (int ks = 0; ks < 2; ks++) {
            uint32_t ah[4][4], al[4][4], bh[4][2], bl[4][2];
#pragma unroll
            for (int mi = 0; mi < 4; mi++) {
                uint32_t off = (aRow + mi * 16) * ROWB + (aChk + 2 * ks) * 16;
                ldsm_x4(ah[mi], sAhi + off);
                ldsm_x4(al[mi], sAlo + off);
            }
#pragma unroll
            for (int ni = 0; ni < 4; ni++) {
                uint32_t off = (bRow + ni * 8) * ROWB + (bChk + 2 * ks) * 16;
                ldsm_x2(bh[ni], sBhi + off);
                ldsm_x2(bl[ni], sBlo + off);
            }
#pragma unroll
            for (int mi = 0; mi < 4; mi++)
#pragma unroll
                for (int ni = 0; ni < 4; ni++)
                    mma_bf16(acc[mi][ni], ah[mi], bh[ni]);
#pragma unroll
            for (int mi = 0; mi < 4; mi++)
#pragma unroll
                for (int ni = 0; ni < 4; ni++)
                    mma_bf16(acc[mi][ni], al[mi], bh[ni]);
#pragma unroll
            for (int mi = 0; mi < 4; mi++)
#pragma unroll
                for (int ni = 0; ni < 4; ni++)
                    mma_bf16(acc[mi][ni], ah[mi], bl[ni]);
        }
        __syncthreads();
    }

#pragma unroll
    for (int mi = 0; mi < 4; mi++) {
        const int r0 = cRow + wm * 64 + mi * 16 + (l >> 2);
#pragma unroll
        for (int ni = 0; ni < 4; ni++) {
            const int cc = wn * 32 + ni * 8 + 2 * (l & 3);
            const float b0 = bias[cc], b1 = bias[cc + 1];
            float2 v0 = { acc[mi][ni][0] + b0, acc[mi][ni][1] + b1 };
            float2 v1 = { acc[mi][ni][2] + b0, acc[mi][ni][3] + b1 };
            *reinterpret_cast<float2*>(C + (size_t)r0 * DMODEL + cc) = v0;
            *reinterpret_cast<float2*>(C + (size_t)(r0 + 8) * DMODEL + cc) = v1;
        }
    }
}

__global__ __launch_bounds__(256) void gemm_qkv(
    const __nv_bfloat16* __restrict__ Ahi, const __nv_bfloat16* __restrict__ Alo,
    const __nv_bfloat16* __restrict__ WT,
    const float* __restrict__ bq, const float* __restrict__ bk,
    const float* __restrict__ bv,
    float* __restrict__ Q, float* __restrict__ K, float* __restrict__ V)
{
    extern __shared__ char dsm[];
    const int w    = blockIdx.x >> 2;            // 0..2
    const int ncol = (blockIdx.x & 3) * 128;
    const int cRow = blockIdx.y * 128;
    const size_t WSZ = (size_t)DMODEL * DMODEL;
    const __nv_bfloat16* Bhi = WT + (size_t)(2 * w) * WSZ + (size_t)ncol * DMODEL;
    const __nv_bfloat16* Blo = Bhi + WSZ;
    const float* bias = ((w == 0) ? bq : (w == 1) ? bk : bv) + ncol;
    float* C = ((w == 0) ? Q : (w == 1) ? K : V) + ncol;
    gemm_core(Ahi, Alo, Bhi, Blo, bias, C, cRow, dsm);
}

__global__ __launch_bounds__(256) void gemm_o(
    const __nv_bfloat16* __restrict__ Ahi, const __nv_bfloat16* __restrict__ Alo,
    const __nv_bfloat16* __restrict__ WT, const float* __restrict__ bo,
    float* __restrict__ C)
{
    extern __shared__ char dsm[];
    const int ncol = blockIdx.x * 128;
    const int cRow = blockIdx.y * 128;
    const size_t WSZ = (size_t)DMODEL * DMODEL;
    const __nv_bfloat16* Bhi = WT + (size_t)6 * WSZ + (size_t)ncol * DMODEL;
    const __nv_bfloat16* Blo = Bhi + WSZ;
    gemm_core(Ahi, Alo, Bhi, Blo, bo + ncol, C + ncol, cRow, dsm);
}

// ---------------------------------------------------------------------------
// Banded causal attention (R12 exact): 16 queries/block, 512 thr, 26-row smem
// window (swizzle sigma(c)=c^((c>>3)&3)), cp.async staging with Q-load +
// attn_mean zero-fill overlap.
// ---------------------------------------------------------------------------
__global__ __launch_bounds__(512, 2) void attn_banded(
    const float* __restrict__ Q, const float* __restrict__ K,
    const float* __restrict__ V, const float* __restrict__ td,
    __nv_bfloat16* __restrict__ chi, __nv_bfloat16* __restrict__ clo,
    float* __restrict__ attn_mean)
{
    extern __shared__ float s_kv[];              // [2][WIN][512]
    __shared__ float s_d[MAXLAG + 1];

    const int tid = threadIdx.x;
    const int w = tid >> 5;
    const int l = tid & 31;
    const int blk = blockIdx.x;
    const int b  = blk >> 7;                     // 128 blocks per batch
    const int i0 = (blk & 127) * QBLK;
    const int i  = i0 + w;
    const int bi = blk * QBLK + w;               // global row

    if (tid <= MAXLAG) {
        float x = td[tid];
        float sp = (x > 20.f) ? x : log1pf(expf(x));
        s_d[tid] = -logf(sp + 1e-8f);
    }

    // ---- stage the K/V window via cp.async
    const uint32_t skv = smem_u32(s_kv);
    const uint32_t svoff = WIN * DMODEL * 4;
    const int row0 = i0 - MAXLAG;
    const float* Kb = K + (size_t)b * SEQ * DMODEL;
    const float* Vb = V + (size_t)b * SEQ * DMODEL;
#pragma unroll
    for (int q = 0; q < (WIN * 128 + 511) / 512; q++) {
        int g = tid + q * 512;
        if (g < WIN * 128) {
            int widx = g >> 7, c = g & 127;
            int rg = row0 + widx;
            if (rg >= 0) {
                int slot = c ^ ((c >> 3) & 3);
                uint32_t soff = (uint32_t)(widx * DMODEL + slot * 4) * 4;
                cpasync16(skv + soff,         Kb + (size_t)rg * DMODEL + c * 4);
                cpasync16(skv + svoff + soff, Vb + (size_t)rg * DMODEL + c * 4);
            }
        }
    }
    asm volatile("cp.async.commit_group;" ::: "memory");

    // ---- overlap: zero-fill this block's 16 attn_mean rows
    float* ablk = attn_mean + (size_t)b * SEQ * SEQ + (size_t)i0 * SEQ;
    {
        float4 z = {0.f, 0.f, 0.f, 0.f};
#pragma unroll
        for (int r = 0; r < QBLK; r++)
            reinterpret_cast<float4*>(ablk + (size_t)r * SEQ)[tid] = z;
    }

    // ---- overlap: load q while the cp.asyncs fly
    const float4* qp = reinterpret_cast<const float4*>(Q + (size_t)bi * DMODEL + 16 * l);
    float4 q0 = qp[0], q1 = qp[1], q2 = qp[2], q3 = qp[3];

    asm volatile("cp.async.wait_group 0;" ::: "memory");
    __syncthreads();

    const float* sK = s_kv;
    const float* sV = s_kv + WIN * DMODEL;

    int sl[4];
#pragma unroll
    for (int t = 0; t < 4; t++) {
        int c = 4 * l + t;
        sl[t] = (c ^ ((c >> 3) & 3)) * 4;
    }

    const int jstart = (i > MAXLAG) ? (i - MAXLAG) : 0;
    const int nj = i - jstart + 1;

    float sc[MAXLAG + 1];
#pragma unroll
    for (int jj = 0; jj <= MAXLAG; jj++) {
        if (jj < nj) {
            const float* kr = sK + (size_t)(jstart + jj - row0) * DMODEL;
            float4 k0 = *reinterpret_cast<const float4*>(kr + sl[0]);
            float4 k1 = *reinterpret_cast<const float4*>(kr + sl[1]);
            float4 k2 = *reinterpret_cast<const float4*>(kr + sl[2]);
            float4 k3 = *reinterpret_cast<const float4*>(kr + sl[3]);
            float d = q0.x * k0.x + q0.y * k0.y + q0.z * k0.z + q0.w * k0.w
                    + q1.x * k1.x + q1.y * k1.y + q1.z * k1.z + q1.w * k1.w
                    + q2.x * k2.x + q2.y * k2.y + q2.z * k2.z + q2.w * k2.w
                    + q3.x * k3.x + q3.y * k3.y + q3.z * k3.z + q3.w * k3.w;
            d += __shfl_xor_sync(0xffffffffu, d, 1);
            d += __shfl_xor_sync(0xffffffffu, d, 2);
            sc[jj] = d * 0.125f + s_d[i - (jstart + jj)];
        } else {
            sc[jj] = -1e30f;
        }
    }

    float mx = sc[0];
#pragma unroll
    for (int jj = 1; jj <= MAXLAG; jj++) mx = fmaxf(mx, sc[jj]);
    float sum = 0.f;
#pragma unroll
    for (int jj = 0; jj <= MAXLAG; jj++) {
        sc[jj] = expf(sc[jj] - mx);
        sum += sc[jj];
    }
    const float inv = 1.f / sum;

    float4 c0 = {0,0,0,0}, c1 = {0,0,0,0}, c2 = {0,0,0,0}, c3 = {0,0,0,0};
#pragma unroll
    for (int jj = 0; jj <= MAXLAG; jj++) {
        if (jj < nj) {
            const float p = sc[jj] * inv;
            sc[jj] = p;
            const float* vr = sV + (size_t)(jstart + jj - row0) * DMODEL;
            float4 v0 = *reinterpret_cast<const float4*>(vr + sl[0]);
            float4 v1 = *reinterpret_cast<const float4*>(vr + sl[1]);
            float4 v2 = *reinterpret_cast<const float4*>(vr + sl[2]);
            float4 v3 = *reinterpret_cast<const float4*>(vr + sl[3]);
            c0.x = fmaf(p, v0.x, c0.x); c0.y = fmaf(p, v0.y, c0.y);
            c0.z = fmaf(p, v0.z, c0.z); c0.w = fmaf(p, v0.w, c0.w);
            c1.x = fmaf(p, v1.x, c1.x); c1.y = fmaf(p, v1.y, c1.y);
            c1.z = fmaf(p, v1.z, c1.z); c1.w = fmaf(p, v1.w, c1.w);
            c2.x = fmaf(p, v2.x, c2.x); c2.y = fmaf(p, v2.y, c2.y);
            c2.z = fmaf(p, v2.z, c2.z); c2.w = fmaf(p, v2.w, c2.w);
            c3.x = fmaf(p, v3.x, c3.x); c3.y = fmaf(p, v3.y, c3.y);
            c3.z = fmaf(p, v3.z, c3.z); c3.w = fmaf(p, v3.w, c3.w);
        } else {
            sc[jj] = 0.f;
        }
    }

    // ctx as bf16 hi/lo
    {
        __nv_bfloat162* hp = reinterpret_cast<__nv_bfloat162*>(chi) + (size_t)bi * 256 + 8 * l;
        __nv_bfloat162* lp = reinterpret_cast<__nv_bfloat162*>(clo) + (size_t)bi * 256 + 8 * l;
        __nv_bfloat162 h, lo2;
        split2(c0.x, c0.y, h, lo2); hp[0] = h; lp[0] = lo2;
        split2(c0.z, c0.w, h, lo2); hp[1] = h; lp[1] = lo2;
        split2(c1.x, c1.y, h, lo2); hp[2] = h; lp[2] = lo2;
        split2(c1.z, c1.w, h, lo2); hp[3] = h; lp[3] = lo2;
        split2(c2.x, c2.y, h, lo2); hp[4] = h; lp[4] = lo2;
        split2(c2.z, c2.w, h, lo2); hp[5] = h; lp[5] = lo2;
        split2(c3.x, c3.y, h, lo2); hp[6] = h; lp[6] = lo2;
        split2(c3.z, c3.w, h, lo2); hp[7] = h; lp[7] = lo2;
    }

    // attn_mean: butterfly xor 4/8/16 sums each head exactly once
    float* arow = attn_mean + (size_t)b * SEQ * SEQ + (size_t)i * SEQ;
#pragma unroll
    for (int jj = 0; jj <= MAXLAG; jj++) {
        float P = sc[jj];
        P += __shfl_xor_sync(0xffffffffu, P, 4);
        P += __shfl_xor_sync(0xffffffffu, P, 8);
        P += __shfl_xor_sync(0xffffffffu, P, 16);
        if (l == jj && jj < nj)
            arow[jstart + jj] = P * (1.f / NHEADS);
    }
}

// ---------------------------------------------------------------------------
extern "C" void kernel_launch(void* const* d_in, const int* in_sizes, int n_in,
                              void* d_out, int out_size)
{
    const float* x  = (const float*)d_in[0];
    const float* Wq = (const float*)d_in[1];
    const float* bq = (const float*)d_in[2];
    const float* Wk = (const float*)d_in[3];
    const float* bk = (const float*)d_in[4];
    const float* Wv = (const float*)d_in[5];
    const float* bv = (const float*)d_in[6];
    const float* Wo = (const float*)d_in[7];
    const float* bo = (const float*)d_in[8];
    const float* td = (const float*)d_in[9];

    float* out_ptr  = (float*)d_out;
    float* attn_ptr = out_ptr + (size_t)BATCH * SEQ * DMODEL;

    __nv_bfloat16 *Xhi, *Xlo, *Chi, *Clo, *WT;
    float *Qs, *Ks, *Vs;
    cudaGetSymbolAddress((void**)&Xhi, g_Xhi);
    cudaGetSymbolAddress((void**)&Xlo, g_Xlo);
    cudaGetSymbolAddress((void**)&Chi, g_Chi);
    cudaGetSymbolAddress((void**)&Clo, g_Clo);
    cudaGetSymbolAddress((void**)&WT,  g_WT);
    cudaGetSymbolAddress((void**)&Qs,  g_Q);
    cudaGetSymbolAddress((void**)&Ks,  g_K);
    cudaGetSymbolAddress((void**)&Vs,  g_V);

    cudaFuncSetAttribute(gemm_qkv,
                         cudaFuncAttributeMaxDynamicSharedMemorySize, GSMEM_DYN);
    cudaFuncSetAttribute(gemm_o,
                         cudaFuncAttributeMaxDynamicSharedMemorySize, GSMEM_DYN);
    cudaFuncSetAttribute(attn_banded,
                         cudaFuncAttributeMaxDynamicSharedMemorySize, ASMEM);

    // 1) merged conversions (X split + 4 weight transpose/splits, one launch)
    convert_all<<<XBLOCKS + 1024, 256>>>(x, Wq, Wk, Wv, Wo, Xhi, Xlo, WT);

    // 2) fused QKV projection -> separate Q/K/V buffers
    dim3 gq(12, MTOT / 128);
    gemm_qkv<<<gq, 256, GSMEM_DYN>>>(Xhi, Xlo, WT, bq, bk, bv, Qs, Ks, Vs);

    // 3) banded attention (16 queries/block; zero-fills its attn_mean rows)
    attn_banded<<<MTOT / QBLK, 512, ASMEM>>>(Qs, Ks, Vs, td, Chi, Clo, attn_ptr);

    // 4) O projection straight into d_out
    dim3 go(DMODEL / 128, MTOT / 128);
    gemm_o<<<go, 256, GSMEM_DYN>>>(Chi, Clo, WT, bo, out_ptr);
}